// round 6
// baseline (speedup 1.0000x reference)
#include <cuda_runtime.h>

// MemoryModule: B=8,L=12,T=36,D=1024,F=3,C=32
//   mq[c,t] = sum_{f,g} Wm[c,f] Wq[c,g] G[t,f,g] + bm[c]*(Wq[c]·XLsum)
//           + bq[c]*(Wm[c]·XHsum[t]) + D*bm[c]*bq[c]
//   o[c,d]  = sum_f Wc[c,f] * (sum_t att[c,t]*xh[t,d,f]) + bc[c]
// v6: k_gram smem-staged (fixes 12-line LDG wavefront blowup),
//     k_out register-blocked + pre-duplicated att pairs (no packing MOVs).

#define Bb 8
#define Ll 12
#define Tt 36
#define Dd 1024
#define Ff 3
#define Cc 32
#define BL (Bb * Ll)
#define DF (Dd * Ff)        // 3072
#define DC 128
#define CHUNKS (Dd / DC)    // 8

__device__ __align__(16) float g_att2[BL * Tt * Cc * 2];  // (a,a) pairs [bl][t][c]
__device__ float g_G[4 * BL * Tt * 12];                    // 4 d-slices of G[9]+XHsum[3]

#define FFMA2(d, a, b) \
    asm("fma.rn.f32x2 %0, %1, %2, %0;" : "+l"(d) : "l"(a), "l"(b))

#define CP16(dst, src) \
    asm volatile("cp.async.cg.shared.global [%0], [%1], 16;" :: "r"(dst), "l"(src))

union U2F { unsigned long long u; float2 f; };

// ---------------------------------------------------------------------------
// k_gram: CTA = (tg 0..8, dh 0..1, bl). Stage 4 xh t-rows (d-half, 6KB each)
// + xl d-half (6KB) = 30KB via contiguous cp.async. Warp task = (t, 256-d seg).
// Conflict-free scalar LDS at 12B stride. Grid (18,96) x 256.
// ---------------------------------------------------------------------------
#define G_TROWS 4
#define G_DHALF 1536                       // floats per d-half row (512 d * 3)
#define G_SMEM_F (G_TROWS * G_DHALF + G_DHALF)   // 7680 floats = 30 KB

__global__ __launch_bounds__(256) void k_gram(
    const float* __restrict__ xh_g, const float* __restrict__ xl_g)
{
    extern __shared__ float sg[];
    float* s_xh = sg;                       // [4][1536]
    float* s_xl = sg + G_TROWS * G_DHALF;   // [1536]

    int bx = blockIdx.x, bl = blockIdx.y;
    int tg = bx % 9, dh = bx / 9;
    int tid = threadIdx.x, w = tid >> 5, lane = tid & 31;

    const float* xh_base = xh_g + ((size_t)bl * Tt + tg * G_TROWS) * DF + dh * G_DHALF;
    const float* xl_base = xl_g + (size_t)bl * DF + dh * G_DHALF;

    for (int i = tid; i < G_SMEM_F / 4; i += 256) {
        const float* src;
        unsigned dst;
        if (i < G_TROWS * G_DHALF / 4) {
            int row = i / (G_DHALF / 4);            // /384
            int col = (i - row * (G_DHALF / 4)) * 4;
            src = xh_base + (size_t)row * DF + col;
            dst = (unsigned)__cvta_generic_to_shared(s_xh + row * G_DHALF + col);
        } else {
            int j = (i - G_TROWS * G_DHALF / 4) * 4;
            src = xl_base + j;
            dst = (unsigned)__cvta_generic_to_shared(s_xl + j);
        }
        CP16(dst, src);
    }
    asm volatile("cp.async.commit_group;");
    asm volatile("cp.async.wait_group 0;");
    __syncthreads();

    int tr = w >> 1, dseg = w & 1;          // warp task
    const float* xp = s_xh + tr * G_DHALF + dseg * 768;
    const float* lp = s_xl + dseg * 768;

    float V[12];
    #pragma unroll
    for (int j = 0; j < 12; j++) V[j] = 0.0f;

    #pragma unroll
    for (int it = 0; it < 8; it++) {
        int o = it * 96 + lane * 3;
        float a0 = xp[o + 0], a1 = xp[o + 1], a2 = xp[o + 2];
        float b0 = lp[o + 0], b1 = lp[o + 1], b2 = lp[o + 2];
        V[0] = fmaf(a0, b0, V[0]); V[1] = fmaf(a0, b1, V[1]); V[2] = fmaf(a0, b2, V[2]);
        V[3] = fmaf(a1, b0, V[3]); V[4] = fmaf(a1, b1, V[4]); V[5] = fmaf(a1, b2, V[5]);
        V[6] = fmaf(a2, b0, V[6]); V[7] = fmaf(a2, b1, V[7]); V[8] = fmaf(a2, b2, V[8]);
        V[9] += a0; V[10] += a1; V[11] += a2;
    }

    #pragma unroll
    for (int j = 0; j < 12; j++) {
        #pragma unroll
        for (int o = 16; o; o >>= 1) V[j] += __shfl_down_sync(~0u, V[j], o);
    }
    if (lane == 0) {
        int t = tg * G_TROWS + tr;
        int slot = dh * 2 + dseg;
        float* gp = g_G + (((size_t)slot * BL + bl) * Tt + t) * 12;
        #pragma unroll
        for (int j = 0; j < 12; j++) gp[j] = V[j];
    }
}

// ---------------------------------------------------------------------------
// k_score: per bl: sum 4 G slices + XLsum + scores + softmax -> g_att2 pairs.
// ---------------------------------------------------------------------------
__global__ __launch_bounds__(256) void k_score(
    const float* __restrict__ xl_g,
    const float* __restrict__ Wq, const float* __restrict__ bq,
    const float* __restrict__ Wm, const float* __restrict__ bm)
{
    __shared__ float s_G[Tt][12];
    __shared__ float s_mq[Cc][Tt];
    __shared__ float s_XL[3];

    int bl = blockIdx.x;
    int tid = threadIdx.x, w = tid >> 5, lane = tid & 31;

    if (tid < 3) s_XL[tid] = 0.0f;
    for (int i = tid; i < Tt * 12; i += 256)
        ((float*)s_G)[i] = g_G[((size_t)0 * BL + bl) * Tt * 12 + i]
                         + g_G[((size_t)1 * BL + bl) * Tt * 12 + i]
                         + g_G[((size_t)2 * BL + bl) * Tt * 12 + i]
                         + g_G[((size_t)3 * BL + bl) * Tt * 12 + i];

    {
        const float* xl = xl_g + (size_t)bl * DF;
        float x0 = 0, x1 = 0, x2 = 0;
        for (int d = tid; d < Dd; d += 256) {
            x0 += xl[d * 3 + 0]; x1 += xl[d * 3 + 1]; x2 += xl[d * 3 + 2];
        }
        #pragma unroll
        for (int o = 16; o; o >>= 1) {
            x0 += __shfl_down_sync(~0u, x0, o);
            x1 += __shfl_down_sync(~0u, x1, o);
            x2 += __shfl_down_sync(~0u, x2, o);
        }
        __syncthreads();
        if (lane == 0) {
            atomicAdd(&s_XL[0], x0); atomicAdd(&s_XL[1], x1); atomicAdd(&s_XL[2], x2);
        }
    }
    __syncthreads();

    for (int i = tid; i < Cc * Tt; i += 256) {
        int c = i / Tt, t = i - c * Tt;
        float wm0 = Wm[c * 3 + 0], wm1 = Wm[c * 3 + 1], wm2 = Wm[c * 3 + 2];
        float wq0 = Wq[c * 3 + 0], wq1 = Wq[c * 3 + 1], wq2 = Wq[c * 3 + 2];
        float bmc = bm[c], bqc = bq[c];
        const float* Gp = s_G[t];
        float v = wm0 * (wq0 * Gp[0] + wq1 * Gp[1] + wq2 * Gp[2])
                + wm1 * (wq0 * Gp[3] + wq1 * Gp[4] + wq2 * Gp[5])
                + wm2 * (wq0 * Gp[6] + wq1 * Gp[7] + wq2 * Gp[8])
                + bmc * (wq0 * s_XL[0] + wq1 * s_XL[1] + wq2 * s_XL[2])
                + bqc * (wm0 * Gp[9] + wm1 * Gp[10] + wm2 * Gp[11])
                + (float)Dd * bmc * bqc;
        s_mq[c][t] = fmaxf(v, 0.0f);
    }
    __syncthreads();

    #pragma unroll
    for (int k = 0; k < 4; k++) {
        int c = w + 8 * k;
        float v0 = s_mq[c][lane];
        float v1 = (lane < Tt - 32) ? s_mq[c][lane + 32] : -3.0e38f;
        float mx = fmaxf(v0, v1);
        #pragma unroll
        for (int o = 16; o; o >>= 1) mx = fmaxf(mx, __shfl_xor_sync(~0u, mx, o));
        float e0 = __expf(v0 - mx);
        float e1 = (lane < Tt - 32) ? __expf(v1 - mx) : 0.0f;
        float s = e0 + e1;
        #pragma unroll
        for (int o = 16; o; o >>= 1) s += __shfl_xor_sync(~0u, s, o);
        float inv = 1.0f / s;
        float2* ap = (float2*)g_att2 + (size_t)bl * Tt * Cc;
        float a0 = e0 * inv;
        ap[lane * Cc + c] = make_float2(a0, a0);
        if (lane < Tt - 32) {
            float a1 = e1 * inv;
            ap[(lane + 32) * Cc + c] = make_float2(a1, a1);
        }
    }
}

// ---------------------------------------------------------------------------
// k_out: CTA = (bl, 128-d chunk). Lane = (cg = lane>>3, dp = lane&7):
// 8 channels x 1 d-pair, 24 FFMA2 accumulators. att read as pre-duplicated
// (a,a) u64 pairs -> zero packing MOVs. Per (warp,t): 4 LDS.128 + 3 LDS.64
// + 24 FFMA2. Grid 768 x 256, smem 66KB, 3 CTAs/SM.
// ---------------------------------------------------------------------------
#define SM_TILE_F (Tt * DC * Ff)   // 13824
#define SM_ATT_F  (Tt * Cc * 2)    // 2304 (u64 pairs)
#define SM_XL_F   (DC * Ff)        // 384
#define ROW_CP    (DC * Ff / 4)    // 96
#define T_SPLIT   12

__global__ __launch_bounds__(256, 3) void k_out(
    const float* __restrict__ xl_g, const float* __restrict__ xh_g,
    const float* __restrict__ Wq, const float* __restrict__ bq,
    const float* __restrict__ Wc, const float* __restrict__ bc,
    float* __restrict__ out)
{
    extern __shared__ float sm[];
    float* s_tile = sm;
    float* s_att  = sm + SM_TILE_F;
    float* s_xl   = sm + SM_TILE_F + SM_ATT_F;

    int blk = blockIdx.x;
    int bl = blk / CHUNKS, chunk = blk - bl * CHUNKS;
    int b = bl / Ll, l = bl - b * Ll;
    int tid = threadIdx.x;

    const float* xh_bl   = xh_g + (size_t)bl * Tt * DF + chunk * DC * Ff;
    const float* att_src = (const float*)g_att2 + (size_t)bl * Tt * Cc * 2;
    const float* xl_src  = xl_g + (size_t)bl * DF + chunk * DC * Ff;

    // stage A: att + xl + tile rows [0,12)
    for (int i = tid; i < SM_ATT_F / 4; i += 256)
        CP16((unsigned)__cvta_generic_to_shared(s_att + i * 4), att_src + i * 4);
    if (tid < SM_XL_F / 4)
        CP16((unsigned)__cvta_generic_to_shared(s_xl + tid * 4), xl_src + tid * 4);
    for (int i = tid; i < T_SPLIT * ROW_CP; i += 256) {
        int row = i / ROW_CP, col = (i - row * ROW_CP) * 4;
        CP16((unsigned)__cvta_generic_to_shared(s_tile + row * (DC * Ff) + col),
             xh_bl + (size_t)row * DF + col);
    }
    asm volatile("cp.async.commit_group;");

    // stage B: tile rows [12,36)
    for (int i = tid; i < (Tt - T_SPLIT) * ROW_CP; i += 256) {
        int row = T_SPLIT + i / ROW_CP, col = (i % ROW_CP) * 4;
        CP16((unsigned)__cvta_generic_to_shared(s_tile + row * (DC * Ff) + col),
             xh_bl + (size_t)row * DF + col);
    }
    asm volatile("cp.async.commit_group;");

    int wid = tid >> 5, lane = tid & 31;
    int cg = lane >> 3, dp = lane & 7;
    int dloc = wid * 16 + dp * 2;

    unsigned long long A[24];
    #pragma unroll
    for (int k = 0; k < 24; k++) A[k] = 0ull;

    const unsigned long long* ab = (const unsigned long long*)s_att + cg * 8; // + t*32
    const unsigned long long* tb =
        (const unsigned long long*)(s_tile + dloc * Ff);                       // + t*192

    asm volatile("cp.async.wait_group 1;");
    __syncthreads();

    #pragma unroll 2
    for (int t = 0; t < T_SPLIT; t++) {
        const ulonglong2* ap2 = (const ulonglong2*)(ab + t * 32);
        ulonglong2 p0 = ap2[0], p1 = ap2[1], p2 = ap2[2], p3 = ap2[3];
        unsigned long long x0 = tb[t * 192 + 0];
        unsigned long long x1 = tb[t * 192 + 1];
        unsigned long long x2 = tb[t * 192 + 2];
        unsigned long long av[8] = {p0.x, p0.y, p1.x, p1.y, p2.x, p2.y, p3.x, p3.y};
        #pragma unroll
        for (int k = 0; k < 8; k++) {
            FFMA2(A[3 * k + 0], x0, av[k]);
            FFMA2(A[3 * k + 1], x1, av[k]);
            FFMA2(A[3 * k + 2], x2, av[k]);
        }
    }

    asm volatile("cp.async.wait_group 0;");
    __syncthreads();

    #pragma unroll 2
    for (int t = T_SPLIT; t < Tt; t++) {
        const ulonglong2* ap2 = (const ulonglong2*)(ab + t * 32);
        ulonglong2 p0 = ap2[0], p1 = ap2[1], p2 = ap2[2], p3 = ap2[3];
        unsigned long long x0 = tb[t * 192 + 0];
        unsigned long long x1 = tb[t * 192 + 1];
        unsigned long long x2 = tb[t * 192 + 2];
        unsigned long long av[8] = {p0.x, p0.y, p1.x, p1.y, p2.x, p2.y, p3.x, p3.y};
        #pragma unroll
        for (int k = 0; k < 8; k++) {
            FFMA2(A[3 * k + 0], x0, av[k]);
            FFMA2(A[3 * k + 1], x1, av[k]);
            FFMA2(A[3 * k + 2], x2, av[k]);
        }
    }

    // epilogue: q + Wc·H + bc, 2 d's per channel, 8 channels per lane
    int dglob = chunk * DC + dloc;
    const float* xp = s_xl + dloc * Ff;
    float x00 = xp[0], x01 = xp[1], x02 = xp[2];
    float x10 = xp[3], x11 = xp[4], x12 = xp[5];

    #pragma unroll
    for (int k = 0; k < 8; k++) {
        int c = cg * 8 + k;
        float wc0 = Wc[c * 3 + 0], wc1 = Wc[c * 3 + 1], wc2 = Wc[c * 3 + 2];
        float wq0 = Wq[c * 3 + 0], wq1 = Wq[c * 3 + 1], wq2 = Wq[c * 3 + 2];
        float bcc = bc[c], bqc = bq[c];

        U2F p0, p1, p2;
        p0.u = A[3 * k + 0]; p1.u = A[3 * k + 1]; p2.u = A[3 * k + 2];
        // pairs: p0=(d0f0,d0f1) p1=(d0f2,d1f0) p2=(d1f1,d1f2)
        float o0 = fmaf(wc2, p1.f.x, fmaf(wc1, p0.f.y, fmaf(wc0, p0.f.x, bcc)));
        float o1 = fmaf(wc2, p2.f.y, fmaf(wc1, p2.f.x, fmaf(wc0, p1.f.y, bcc)));
        float q0 = fmaf(wq2, x02, fmaf(wq1, x01, fmaf(wq0, x00, bqc)));
        float q1 = fmaf(wq2, x12, fmaf(wq1, x11, fmaf(wq0, x10, bqc)));

        float2 res = make_float2(q0 + o0, q1 + o1);
        *(float2*)(out + (((size_t)b * Cc + c) * Ll + l) * Dd + dglob) = res;
    }
}

extern "C" void kernel_launch(void* const* d_in, const int* in_sizes, int n_in,
                              void* d_out, int out_size)
{
    const float* xl = (const float*)d_in[0];
    const float* xh = (const float*)d_in[1];
    const float* Wq = (const float*)d_in[2];
    const float* bq = (const float*)d_in[3];
    const float* Wm = (const float*)d_in[4];
    const float* bm = (const float*)d_in[5];
    const float* Wc = (const float*)d_in[6];
    const float* bc = (const float*)d_in[7];
    float* out = (float*)d_out;

    static int attr_set = 0;
    if (!attr_set) {
        cudaFuncSetAttribute(k_out, cudaFuncAttributeMaxDynamicSharedMemorySize,
                             (SM_TILE_F + SM_ATT_F + SM_XL_F) * 4);
        attr_set = 1;
    }

    k_gram<<<dim3(18, BL), 256, G_SMEM_F * 4>>>(xh, xl);
    k_score<<<BL, 256>>>(xl, Wq, bq, Wm, bm);
    k_out<<<BL * CHUNKS, 256, (SM_TILE_F + SM_ATT_F + SM_XL_F) * 4>>>(
        xl, xh, Wq, bq, Wc, bc, out);
}

// round 8
// speedup vs baseline: 1.1834x; 1.1834x over previous
#include <cuda_runtime.h>

// MemoryModule: B=8,L=12,T=36,D=1024,F=3,C=32
//   mq[c,t] = sum_{f,g} Wm[c,f] Wq[c,g] G[t,f,g] + bm[c]*(Wq[c]·XLsum)
//           + bq[c]*(Wm[c]·XHsum[t]) + D*bm[c]*bq[c]
//   o[c,d]  = sum_f Wc[c,f] * (sum_t att[c,t]*xh[t,d,f]) + bc[c]
// v8: v7 with copy bugs fixed (att copy covered 256/288 cp16; stage A row
//     over-copy). Div/mod-free copies, explicit mov.b64 packing.

#define Bb 8
#define Ll 12
#define Tt 36
#define Dd 1024
#define Ff 3
#define Cc 32
#define BL (Bb * Ll)
#define DF (Dd * Ff)        // 3072
#define DC 128
#define CHUNKS (Dd / DC)    // 8

__device__ __align__(16) float g_attf[BL * Tt * Cc];   // plain f32 att [bl][t][c]
__device__ float g_G[4 * BL * Tt * 12];                 // 4 d-slices of G[9]+XHsum[3]

#define FFMA2(d, a, b) \
    asm("fma.rn.f32x2 %0, %1, %2, %0;" : "+l"(d) : "l"(a), "l"(b))

#define PACKDUP(d, s) \
    asm("mov.b64 %0, {%1, %1};" : "=l"(d) : "f"(s))

#define CP16(dst, src) \
    asm volatile("cp.async.cg.shared.global [%0], [%1], 16;" :: "r"(dst), "l"(src))

union U2F { unsigned long long u; float2 f; };

// ---------------------------------------------------------------------------
// k_gram: CTA = (tg 0..8, dh 0..1, bl). Stage 4 xh t-rows (d-half, 6KB each)
// + xl d-half (6KB) = 30KB via structured cp.async (no div/mod).
// Warp task = (t, 256-d seg); scalar LDS at 12B stride (conflict-free).
// Grid (18,96) x 256.
// ---------------------------------------------------------------------------
#define G_TROWS 4
#define G_DHALF 1536                              // floats per d-half row
#define G_SMEM_F (G_TROWS * G_DHALF + G_DHALF)    // 7680 floats = 30 KB

__global__ __launch_bounds__(256) void k_gram(
    const float* __restrict__ xh_g, const float* __restrict__ xl_g)
{
    extern __shared__ float sg[];
    float* s_xh = sg;                       // [4][1536]
    float* s_xl = sg + G_TROWS * G_DHALF;   // [1536]

    int bx = blockIdx.x, bl = blockIdx.y;
    int tg = bx % 9, dh = bx / 9;
    int tid = threadIdx.x, w = tid >> 5, lane = tid & 31;

    const float* xh_base = xh_g + ((size_t)bl * Tt + tg * G_TROWS) * DF + dh * G_DHALF;
    const float* xl_base = xl_g + (size_t)bl * DF + dh * G_DHALF;

    // structured copy: 5 rows x 12 segs of 32 cp16; warp w takes segs w, w+8
    #pragma unroll
    for (int r = 0; r < 5; r++) {
        const float* sb = (r < G_TROWS) ? xh_base + (size_t)r * DF : xl_base;
        float* db = (r < G_TROWS) ? s_xh + r * G_DHALF : s_xl;
        #pragma unroll
        for (int s = 0; s < 2; s++) {
            int seg = w + s * 8;
            if (seg < 12) {
                int off = seg * 128 + lane * 4;
                CP16((unsigned)__cvta_generic_to_shared(db + off), sb + off);
            }
        }
    }
    asm volatile("cp.async.commit_group;");
    asm volatile("cp.async.wait_group 0;");
    __syncthreads();

    int tr = w >> 1, dseg = w & 1;          // warp task: t-row, 256-d segment
    const float* xp = s_xh + tr * G_DHALF + dseg * 768;
    const float* lp = s_xl + dseg * 768;

    float V[12];
    #pragma unroll
    for (int j = 0; j < 12; j++) V[j] = 0.0f;

    #pragma unroll
    for (int it = 0; it < 8; it++) {
        int o = it * 96 + lane * 3;
        float a0 = xp[o + 0], a1 = xp[o + 1], a2 = xp[o + 2];
        float b0 = lp[o + 0], b1 = lp[o + 1], b2 = lp[o + 2];
        V[0] = fmaf(a0, b0, V[0]); V[1] = fmaf(a0, b1, V[1]); V[2] = fmaf(a0, b2, V[2]);
        V[3] = fmaf(a1, b0, V[3]); V[4] = fmaf(a1, b1, V[4]); V[5] = fmaf(a1, b2, V[5]);
        V[6] = fmaf(a2, b0, V[6]); V[7] = fmaf(a2, b1, V[7]); V[8] = fmaf(a2, b2, V[8]);
        V[9] += a0; V[10] += a1; V[11] += a2;
    }

    #pragma unroll
    for (int j = 0; j < 12; j++) {
        #pragma unroll
        for (int o = 16; o; o >>= 1) V[j] += __shfl_down_sync(~0u, V[j], o);
    }
    if (lane == 0) {
        int t = tg * G_TROWS + tr;
        int slot = dh * 2 + dseg;
        float* gp = g_G + (((size_t)slot * BL + bl) * Tt + t) * 12;
        #pragma unroll
        for (int j = 0; j < 12; j++) gp[j] = V[j];
    }
}

// ---------------------------------------------------------------------------
// k_score: per bl: sum 4 G slices + XLsum + scores + softmax -> g_attf.
// ---------------------------------------------------------------------------
__global__ __launch_bounds__(256) void k_score(
    const float* __restrict__ xl_g,
    const float* __restrict__ Wq, const float* __restrict__ bq,
    const float* __restrict__ Wm, const float* __restrict__ bm)
{
    __shared__ float s_G[Tt][12];
    __shared__ float s_mq[Cc][Tt];
    __shared__ float s_XL[3];

    int bl = blockIdx.x;
    int tid = threadIdx.x, w = tid >> 5, lane = tid & 31;

    if (tid < 3) s_XL[tid] = 0.0f;
    for (int i = tid; i < Tt * 12; i += 256)
        ((float*)s_G)[i] = g_G[((size_t)0 * BL + bl) * Tt * 12 + i]
                         + g_G[((size_t)1 * BL + bl) * Tt * 12 + i]
                         + g_G[((size_t)2 * BL + bl) * Tt * 12 + i]
                         + g_G[((size_t)3 * BL + bl) * Tt * 12 + i];

    {
        const float* xl = xl_g + (size_t)bl * DF;
        float x0 = 0, x1 = 0, x2 = 0;
        for (int d = tid; d < Dd; d += 256) {
            x0 += xl[d * 3 + 0]; x1 += xl[d * 3 + 1]; x2 += xl[d * 3 + 2];
        }
        #pragma unroll
        for (int o = 16; o; o >>= 1) {
            x0 += __shfl_down_sync(~0u, x0, o);
            x1 += __shfl_down_sync(~0u, x1, o);
            x2 += __shfl_down_sync(~0u, x2, o);
        }
        __syncthreads();
        if (lane == 0) {
            atomicAdd(&s_XL[0], x0); atomicAdd(&s_XL[1], x1); atomicAdd(&s_XL[2], x2);
        }
    }
    __syncthreads();

    for (int i = tid; i < Cc * Tt; i += 256) {
        int c = i / Tt, t = i - c * Tt;
        float wm0 = Wm[c * 3 + 0], wm1 = Wm[c * 3 + 1], wm2 = Wm[c * 3 + 2];
        float wq0 = Wq[c * 3 + 0], wq1 = Wq[c * 3 + 1], wq2 = Wq[c * 3 + 2];
        float bmc = bm[c], bqc = bq[c];
        const float* Gp = s_G[t];
        float v = wm0 * (wq0 * Gp[0] + wq1 * Gp[1] + wq2 * Gp[2])
                + wm1 * (wq0 * Gp[3] + wq1 * Gp[4] + wq2 * Gp[5])
                + wm2 * (wq0 * Gp[6] + wq1 * Gp[7] + wq2 * Gp[8])
                + bmc * (wq0 * s_XL[0] + wq1 * s_XL[1] + wq2 * s_XL[2])
                + bqc * (wm0 * Gp[9] + wm1 * Gp[10] + wm2 * Gp[11])
                + (float)Dd * bmc * bqc;
        s_mq[c][t] = fmaxf(v, 0.0f);
    }
    __syncthreads();

    #pragma unroll
    for (int k = 0; k < 4; k++) {
        int c = w + 8 * k;
        float v0 = s_mq[c][lane];
        float v1 = (lane < Tt - 32) ? s_mq[c][lane + 32] : -3.0e38f;
        float mx = fmaxf(v0, v1);
        #pragma unroll
        for (int o = 16; o; o >>= 1) mx = fmaxf(mx, __shfl_xor_sync(~0u, mx, o));
        float e0 = __expf(v0 - mx);
        float e1 = (lane < Tt - 32) ? __expf(v1 - mx) : 0.0f;
        float s = e0 + e1;
        #pragma unroll
        for (int o = 16; o; o >>= 1) s += __shfl_xor_sync(~0u, s, o);
        float inv = 1.0f / s;
        float* ap = g_attf + (size_t)bl * Tt * Cc;
        ap[lane * Cc + c] = e0 * inv;
        if (lane < Tt - 32) ap[(lane + 32) * Cc + c] = e1 * inv;
    }
}

// ---------------------------------------------------------------------------
// k_out: CTA = (bl, 128-d chunk). Lane = (cg = lane>>3, dp = lane&7):
// 8 channels x 1 d-pair, 24 FFMA2 accumulators. Structured copy loops,
// explicit mov.b64 packing. Grid 768 x 256, smem ~61KB, 3 CTAs/SM.
// ---------------------------------------------------------------------------
#define SM_TILE_F (Tt * DC * Ff)   // 13824
#define SM_ATT_F  (Tt * Cc)        // 1152 floats = 288 cp16
#define SM_XL_F   (DC * Ff)        // 384 floats = 96 cp16
#define T_SPLIT   12

__global__ __launch_bounds__(256, 3) void k_out(
    const float* __restrict__ xl_g, const float* __restrict__ xh_g,
    const float* __restrict__ Wq, const float* __restrict__ bq,
    const float* __restrict__ Wc, const float* __restrict__ bc,
    float* __restrict__ out)
{
    extern __shared__ float sm[];
    float* s_tile = sm;
    float* s_att  = sm + SM_TILE_F;
    float* s_xl   = sm + SM_TILE_F + SM_ATT_F;

    int blk = blockIdx.x;
    int bl = blk / CHUNKS, chunk = blk - bl * CHUNKS;
    int b = bl / Ll, l = bl - b * Ll;
    int tid = threadIdx.x;
    int wid = tid >> 5, lane = tid & 31;

    const float* xh_bl   = xh_g + (size_t)bl * Tt * DF + chunk * DC * Ff;
    const float* att_src = g_attf + (size_t)bl * Tt * Cc;
    const float* xl_src  = xl_g + (size_t)bl * DF + chunk * DC * Ff;

    // ---- stage A: att (288 cp16, FULL coverage) + xl (96 cp16) + rows [0,12) ----
    {
        CP16((unsigned)__cvta_generic_to_shared(s_att + tid * 4), att_src + tid * 4);
        int i2 = tid + 256;                 // threads 0..31 cover cp16 256..287
        if (i2 < 288)
            CP16((unsigned)__cvta_generic_to_shared(s_att + i2 * 4), att_src + i2 * 4);
        int j = tid - 160;                  // threads 160..255 -> xl cp16 0..95
        if (j >= 0)
            CP16((unsigned)__cvta_generic_to_shared(s_xl + j * 4), xl_src + j * 4);
    }
    // tile rows [0,12): warp w takes rows w (and w+8 if < 12); 3 segs per row
    #pragma unroll
    for (int rr = 0; rr < 2; rr++) {
        int r = wid + rr * 8;
        if (r < T_SPLIT) {
            const float* sb = xh_bl + (size_t)r * DF;
            float* db = s_tile + r * (DC * Ff);
            #pragma unroll
            for (int s = 0; s < 3; s++) {
                int off = s * 128 + lane * 4;
                CP16((unsigned)__cvta_generic_to_shared(db + off), sb + off);
            }
        }
    }
    asm volatile("cp.async.commit_group;");

    // ---- stage B: tile rows [12,36): warp w takes rows 12+w, 20+w, 28+w ----
    #pragma unroll
    for (int rr = 0; rr < 3; rr++) {
        int r = T_SPLIT + wid + rr * 8;
        const float* sb = xh_bl + (size_t)r * DF;
        float* db = s_tile + r * (DC * Ff);
        #pragma unroll
        for (int s = 0; s < 3; s++) {
            int off = s * 128 + lane * 4;
            CP16((unsigned)__cvta_generic_to_shared(db + off), sb + off);
        }
    }
    asm volatile("cp.async.commit_group;");

    int cg = lane >> 3, dp = lane & 7;
    int dloc = wid * 16 + dp * 2;

    unsigned long long A[24];
    #pragma unroll
    for (int k = 0; k < 24; k++) A[k] = 0ull;

    const float* ab = s_att + cg * 8;                    // + t*32
    const unsigned long long* tb =
        (const unsigned long long*)(s_tile + dloc * Ff); // + t*192 (u64 units)

    asm volatile("cp.async.wait_group 1;");
    __syncthreads();

    #pragma unroll 2
    for (int t = 0; t < T_SPLIT; t++) {
        float4 a0 = *(const float4*)(ab + t * Cc);
        float4 a1 = *(const float4*)(ab + t * Cc + 4);
        unsigned long long x0 = tb[t * 192 + 0];
        unsigned long long x1 = tb[t * 192 + 1];
        unsigned long long x2 = tb[t * 192 + 2];
        unsigned long long p0, p1, p2, p3, p4, p5, p6, p7;
        PACKDUP(p0, a0.x); PACKDUP(p1, a0.y); PACKDUP(p2, a0.z); PACKDUP(p3, a0.w);
        PACKDUP(p4, a1.x); PACKDUP(p5, a1.y); PACKDUP(p6, a1.z); PACKDUP(p7, a1.w);
        unsigned long long av[8] = {p0, p1, p2, p3, p4, p5, p6, p7};
        #pragma unroll
        for (int k = 0; k < 8; k++) {
            FFMA2(A[3 * k + 0], x0, av[k]);
            FFMA2(A[3 * k + 1], x1, av[k]);
            FFMA2(A[3 * k + 2], x2, av[k]);
        }
    }

    asm volatile("cp.async.wait_group 0;");
    __syncthreads();

    #pragma unroll 2
    for (int t = T_SPLIT; t < Tt; t++) {
        float4 a0 = *(const float4*)(ab + t * Cc);
        float4 a1 = *(const float4*)(ab + t * Cc + 4);
        unsigned long long x0 = tb[t * 192 + 0];
        unsigned long long x1 = tb[t * 192 + 1];
        unsigned long long x2 = tb[t * 192 + 2];
        unsigned long long p0, p1, p2, p3, p4, p5, p6, p7;
        PACKDUP(p0, a0.x); PACKDUP(p1, a0.y); PACKDUP(p2, a0.z); PACKDUP(p3, a0.w);
        PACKDUP(p4, a1.x); PACKDUP(p5, a1.y); PACKDUP(p6, a1.z); PACKDUP(p7, a1.w);
        unsigned long long av[8] = {p0, p1, p2, p3, p4, p5, p6, p7};
        #pragma unroll
        for (int k = 0; k < 8; k++) {
            FFMA2(A[3 * k + 0], x0, av[k]);
            FFMA2(A[3 * k + 1], x1, av[k]);
            FFMA2(A[3 * k + 2], x2, av[k]);
        }
    }

    // epilogue: q + Wc·H + bc, 2 d's per channel, 8 channels per lane
    int dglob = chunk * DC + dloc;
    const float* xp = s_xl + dloc * Ff;
    float x00 = xp[0], x01 = xp[1], x02 = xp[2];
    float x10 = xp[3], x11 = xp[4], x12 = xp[5];

    #pragma unroll
    for (int k = 0; k < 8; k++) {
        int c = cg * 8 + k;
        float wc0 = Wc[c * 3 + 0], wc1 = Wc[c * 3 + 1], wc2 = Wc[c * 3 + 2];
        float wq0 = Wq[c * 3 + 0], wq1 = Wq[c * 3 + 1], wq2 = Wq[c * 3 + 2];
        float bcc = bc[c], bqc = bq[c];

        U2F p0, p1, p2;
        p0.u = A[3 * k + 0]; p1.u = A[3 * k + 1]; p2.u = A[3 * k + 2];
        // pairs: p0=(d0f0,d0f1) p1=(d0f2,d1f0) p2=(d1f1,d1f2)
        float o0 = fmaf(wc2, p1.f.x, fmaf(wc1, p0.f.y, fmaf(wc0, p0.f.x, bcc)));
        float o1 = fmaf(wc2, p2.f.y, fmaf(wc1, p2.f.x, fmaf(wc0, p1.f.y, bcc)));
        float q0 = fmaf(wq2, x02, fmaf(wq1, x01, fmaf(wq0, x00, bqc)));
        float q1 = fmaf(wq2, x12, fmaf(wq1, x11, fmaf(wq0, x10, bqc)));

        float2 res = make_float2(q0 + o0, q1 + o1);
        *(float2*)(out + (((size_t)b * Cc + c) * Ll + l) * Dd + dglob) = res;
    }
}

extern "C" void kernel_launch(void* const* d_in, const int* in_sizes, int n_in,
                              void* d_out, int out_size)
{
    const float* xl = (const float*)d_in[0];
    const float* xh = (const float*)d_in[1];
    const float* Wq = (const float*)d_in[2];
    const float* bq = (const float*)d_in[3];
    const float* Wm = (const float*)d_in[4];
    const float* bm = (const float*)d_in[5];
    const float* Wc = (const float*)d_in[6];
    const float* bc = (const float*)d_in[7];
    float* out = (float*)d_out;

    static int attr_set = 0;
    if (!attr_set) {
        cudaFuncSetAttribute(k_gram, cudaFuncAttributeMaxDynamicSharedMemorySize,
                             G_SMEM_F * 4);
        cudaFuncSetAttribute(k_out, cudaFuncAttributeMaxDynamicSharedMemorySize,
                             (SM_TILE_F + SM_ATT_F + SM_XL_F) * 4);
        attr_set = 1;
    }

    k_gram<<<dim3(18, BL), 256, G_SMEM_F * 4>>>(xh, xl);
    k_score<<<BL, 256>>>(xl, Wq, bq, Wm, bm);
    k_out<<<BL * CHUNKS, 256, (SM_TILE_F + SM_ATT_F + SM_XL_F) * 4>>>(
        xl, xh, Wq, bq, Wc, bc, out);
}